// round 1
// baseline (speedup 1.0000x reference)
#include <cuda_runtime.h>
#include <cstddef>

// Problem shape (fixed by dataset): x (8,64,256,256) f32, kernel 4x4 f32, factor=2
// Output: (8,64,512,512) f32.
//
// upfirdn2d(up=2, pad0=2, pad1=1) reduces to: each output pixel = 4-tap dot
// with a parity-selected 2x2 quadrant of the 4x4 kernel over a 2x2 input
// neighborhood. Derivation: out[y] = sum_s k[s] * x[(y+1-s)/2] (valid terms only).
//   oy=2m   -> rows m (k-row 1), m-1 (k-row 3)
//   oy=2m+1 -> rows m+1 (k-row 0), m (k-row 2)     (same pattern along x)

#define IH 256
#define IW 256
#define OH 512
#define OW 512

#define TILE_X 64     // input cols per block
#define TILE_Y 16     // input rows per block
#define SM_W   66     // with 1-col halo each side
#define SM_H   18     // with 1-row halo each side
#define SM_STRIDE 68  // pad to avoid bank conflicts

__constant__ float c_k[16];

__global__ __launch_bounds__(256)
void upfirdn2x_kernel(const float* __restrict__ x, float* __restrict__ out)
{
    __shared__ float s[SM_H][SM_STRIDE];

    const int tid = threadIdx.x;
    const int n0 = blockIdx.x * TILE_X;   // input col origin
    const int m0 = blockIdx.y * TILE_Y;   // input row origin
    const int p  = blockIdx.z;            // plane (N*C)

    const float* xp = x + (size_t)p * (IH * IW);
    float* op = out + (size_t)p * (OH * OW);

    // Load haloed input tile; zero-fill outside (implements the FIR padding).
    #pragma unroll
    for (int idx = tid; idx < SM_H * SM_W; idx += 256) {
        const int r = idx / SM_W;
        const int c = idx - r * SM_W;
        const int gr = m0 - 1 + r;
        const int gc = n0 - 1 + c;
        float v = 0.0f;
        if ((unsigned)gr < IH && (unsigned)gc < IW)
            v = __ldg(&xp[gr * IW + gc]);
        s[r][c] = v;
    }
    __syncthreads();

    const int tx = tid & 63;   // 0..63 : input col within tile
    const int ty = tid >> 6;   // 0..3  : row group

    // cache kernel quadrants in registers
    const float k11 = c_k[1*4+1], k13 = c_k[1*4+3], k31 = c_k[3*4+1], k33 = c_k[3*4+3];
    const float k10 = c_k[1*4+0], k12 = c_k[1*4+2], k30 = c_k[3*4+0], k32 = c_k[3*4+2];
    const float k01 = c_k[0*4+1], k03 = c_k[0*4+3], k21 = c_k[2*4+1], k23 = c_k[2*4+3];
    const float k00 = c_k[0*4+0], k02 = c_k[0*4+2], k20 = c_k[2*4+0], k22 = c_k[2*4+2];

    #pragma unroll
    for (int ry = 0; ry < TILE_Y / 4; ry++) {
        const int lr = ty * 4 + ry + 1;  // local row of x[m]
        const int lc = tx + 1;           // local col of x[., n]

        const float xmm = s[lr-1][lc-1], xm0 = s[lr-1][lc], xmp = s[lr-1][lc+1];
        const float x0m = s[lr  ][lc-1], x00 = s[lr  ][lc], x0p = s[lr  ][lc+1];
        const float xpm = s[lr+1][lc-1], xp0 = s[lr+1][lc], xpp = s[lr+1][lc+1];

        // out[2m  ][2n  ], out[2m  ][2n+1]
        const float oEE = k11*x00 + k13*x0m + k31*xm0 + k33*xmm;
        const float oEO = k10*x0p + k12*x00 + k30*xmp + k32*xm0;
        // out[2m+1][2n  ], out[2m+1][2n+1]
        const float oOE = k01*xp0 + k03*xpm + k21*x00 + k23*x0m;
        const float oOO = k00*xpp + k02*xp0 + k20*x0p + k22*x00;

        const int m = m0 + ty * 4 + ry;
        const int n = n0 + tx;
        float2* o0 = reinterpret_cast<float2*>(op + (size_t)(2*m    ) * OW + 2*n);
        float2* o1 = reinterpret_cast<float2*>(op + (size_t)(2*m + 1) * OW + 2*n);
        *o0 = make_float2(oEE, oEO);
        *o1 = make_float2(oOE, oOO);
    }
}

extern "C" void kernel_launch(void* const* d_in, const int* in_sizes, int n_in,
                              void* d_out, int out_size)
{
    const float* x = (const float*)d_in[0];
    const float* k = (const float*)d_in[1];
    // d_in[2] (factor) is baked into the kernel weights & geometry (factor=2).

    const int nc = in_sizes[0] / (IH * IW);   // 8*64 = 512 planes

    // Graph-capturable D2D copy of the 16 FIR weights into constant memory.
    cudaMemcpyToSymbolAsync(c_k, k, 16 * sizeof(float), 0,
                            cudaMemcpyDeviceToDevice);

    dim3 grid(IW / TILE_X, IH / TILE_Y, nc);   // (4, 16, 512)
    upfirdn2x_kernel<<<grid, 256>>>(x, (float*)d_out);
}